// round 15
// baseline (speedup 1.0000x reference)
#include <cuda_runtime.h>
#include <cuda_fp16.h>
#include <mma.h>
using namespace nvcuda;

#define NN 10000
#define NP 10112    /* padded to 79*128 for unguarded wmma stores */
#define NAG 5000
#define EE 160000
#define ET 170000   /* EE + NN self-loops */
#define HH 8
#define CC 128
#define HC 1024     /* HH*CC */
#define COUT 8

// ---------------- scratch (device globals; no allocation allowed) ----------------
__device__ __align__(16) __half g_xlh[NP * HC];   // xl in fp16 (edge-pass stream)
__device__ __align__(16) float g_xr[NP * HC];     // xr fp32 (read once per node)
__device__ __align__(16) float g_h1[NP * CC];     // pad rows stay zero (.bss)
__device__ __align__(16) float g_h2[NP * CC];
__device__ int g_deg[NN];
__device__ int g_wp[NN];
__device__ int g_off[NN + 1];
__device__ int g_csr[ET];
__device__ int g_rows[NAG];

// ---------------- CSR build ----------------
__global__ void k_zero1(int* a, int n) {
    int i = blockIdx.x * blockDim.x + threadIdx.x;
    if (i < n) a[i] = 0;
}

__global__ void k_count(const int* __restrict__ ei, int* __restrict__ deg) {
    int e = blockIdx.x * blockDim.x + threadIdx.x;
    if (e >= ET) return;
    int dst = (e < EE) ? ei[EE + e] : (e - EE);
    atomicAdd(&deg[dst], 1);
}

// 1024 threads, 10 items/thread, warp-shuffle two-level exclusive scan.
// Also seeds wp[i] = off[i] so k_fill needs a single atomicAdd.
__global__ void k_scan(const int* __restrict__ deg, int* __restrict__ off,
                       int* __restrict__ wp) {
    __shared__ int wsum[32];
    int tid = threadIdx.x, lane = tid & 31, wid = tid >> 5;
    int base = tid * 10;
    int loc[10];
    int s = 0;
#pragma unroll
    for (int i = 0; i < 10; i++) {
        int idx = base + i;
        int v = (idx < NN) ? deg[idx] : 0;
        loc[i] = s;
        s += v;
    }
    int inc = s;
#pragma unroll
    for (int o = 1; o < 32; o <<= 1) {
        int t = __shfl_up_sync(0xffffffffu, inc, o);
        if (lane >= o) inc += t;
    }
    if (lane == 31) wsum[wid] = inc;
    __syncthreads();
    if (wid == 0) {
        int w = wsum[lane];
        int wi = w;
#pragma unroll
        for (int o = 1; o < 32; o <<= 1) {
            int t = __shfl_up_sync(0xffffffffu, wi, o);
            if (lane >= o) wi += t;
        }
        wsum[lane] = wi - w;
        if (lane == 31) off[NN] = wi;
    }
    __syncthreads();
    int pre = wsum[wid] + inc - s;
#pragma unroll
    for (int i = 0; i < 10; i++) {
        int idx = base + i;
        if (idx < NN) {
            int v = pre + loc[i];
            off[idx] = v;
            wp[idx] = v;
        }
    }
}

__global__ void k_fill(const int* __restrict__ ei, int* __restrict__ wp,
                       int* __restrict__ csr) {
    int e = blockIdx.x * blockDim.x + threadIdx.x;
    if (e >= ET) return;
    int src, dst;
    if (e < EE) { src = ei[e]; dst = ei[EE + e]; }
    else        { src = e - EE; dst = src; }
    int p = atomicAdd(&wp[dst], 1);
    csr[p] = src;
}

// Drone row gather list (stable compaction).
__global__ void k_rows(const float* __restrict__ x, int* __restrict__ rows) {
    __shared__ int wsum[32];
    int tid = threadIdx.x, lane = tid & 31, wid = tid >> 5;
    int base = tid * 10;
    int loc[10], msk[10];
    int s = 0;
#pragma unroll
    for (int i = 0; i < 10; i++) {
        int idx = base + i;
        int v = (idx < NN && x[idx * 16 + 15] < 0.f) ? 1 : 0;
        msk[i] = v;
        loc[i] = s;
        s += v;
    }
    int inc = s;
#pragma unroll
    for (int o = 1; o < 32; o <<= 1) {
        int t = __shfl_up_sync(0xffffffffu, inc, o);
        if (lane >= o) inc += t;
    }
    if (lane == 31) wsum[wid] = inc;
    __syncthreads();
    if (wid == 0) {
        int w = wsum[lane];
        int wi = w;
#pragma unroll
        for (int o = 1; o < 32; o <<= 1) {
            int t = __shfl_up_sync(0xffffffffu, wi, o);
            if (lane >= o) wi += t;
        }
        wsum[lane] = wi - w;
    }
    __syncthreads();
    int pre = wsum[wid] + inc - s;
#pragma unroll
    for (int i = 0; i < 10; i++) {
        int idx = base + i;
        if (msk[i]) {
            int pos = pre + loc[i];
            if (pos < NAG) rows[pos] = idx;
        }
    }
}

// ---------------- merged fp16 GEMM: z=0: Ch_l = A@Bl+bl (fp16); z=1: Cr = A@Br+br (fp32)
// BM=128, BN=128, BK=16, 256 threads, 8 warps x (64x32), wmma m16n16k16 half, fp32 acc.
// K is a template constant -> fully unrolled mainloop; double-buffered smem.
#define ALDH 24     /* A tile leading dim in halves (16 + 8 pad) */
#define BLDH 136    /* B tile leading dim in halves (128 + 8 pad) */
#define SH_A0 0
#define SH_A1 (128 * ALDH)                 /* 3072 */
#define SH_B0 (2 * 128 * ALDH)             /* 6144 */
#define SH_B1 (SH_B0 + 16 * BLDH)          /* 8320 */
template <int K>
__global__ __launch_bounds__(256)
void k_gemm2(const float* __restrict__ A,
             const float* __restrict__ Bl, const float* __restrict__ bl,
             __half* __restrict__ Chl,
             const float* __restrict__ Br, const float* __restrict__ br,
             float* __restrict__ Cr,
             int M) {
    __shared__ float sh[8192];             // 32KB; halves alias during mainloop
    __half* shh = (__half*)sh;

    const float* B = (blockIdx.z == 0) ? Bl : Br;
    const float* bias = (blockIdx.z == 0) ? bl : br;

    int tid = threadIdx.x;
    int wid = tid >> 5, lane = tid & 31;
    int wm = wid >> 2, wn = wid & 3;
    int m0 = blockIdx.y * 128, n0 = blockIdx.x * 128;

    int arow = tid >> 1;                   // 0..127
    int akb = (tid & 1) * 8;               // 0 or 8
    int brow = tid >> 4;                   // 0..15
    int bcol = (tid & 15) * 8;             // 0..120

    bool aok = (m0 + arow < M);
    const float* aptr = &A[(size_t)(m0 + arow) * K + akb];
    const float* bptr = &B[(size_t)brow * 1024 + n0 + bcol];

    wmma::fragment<wmma::accumulator, 16, 16, 16, float> acc[4][2];
#pragma unroll
    for (int i = 0; i < 4; i++)
#pragma unroll
        for (int j = 0; j < 2; j++) wmma::fill_fragment(acc[i][j], 0.f);

    // prologue: load tile 0 into registers
    float4 ra0 = make_float4(0.f, 0.f, 0.f, 0.f), ra1 = ra0;
    if (aok) { ra0 = *(const float4*)(aptr); ra1 = *(const float4*)(aptr + 4); }
    float4 rb0 = *(const float4*)(bptr);
    float4 rb1 = *(const float4*)(bptr + 4);

#pragma unroll
    for (int k0 = 0; k0 < K; k0 += 16) {
        const int buf = (k0 >> 4) & 1;
        __half* sA = shh + (buf ? SH_A1 : SH_A0);
        __half* sB = shh + (buf ? SH_B1 : SH_B0);
        {
            __half2* ap2 = (__half2*)&sA[arow * ALDH + akb];
            ap2[0] = __floats2half2_rn(ra0.x, ra0.y);
            ap2[1] = __floats2half2_rn(ra0.z, ra0.w);
            ap2[2] = __floats2half2_rn(ra1.x, ra1.y);
            ap2[3] = __floats2half2_rn(ra1.z, ra1.w);
            __half2* bp2 = (__half2*)&sB[brow * BLDH + bcol];
            bp2[0] = __floats2half2_rn(rb0.x, rb0.y);
            bp2[1] = __floats2half2_rn(rb0.z, rb0.w);
            bp2[2] = __floats2half2_rn(rb1.x, rb1.y);
            bp2[3] = __floats2half2_rn(rb1.z, rb1.w);
        }
        __syncthreads();

        // prefetch next tile into registers (overlaps MMA below)
        if (k0 + 16 < K) {
            const float* ap = aptr + k0 + 16;
            ra0 = make_float4(0.f, 0.f, 0.f, 0.f); ra1 = ra0;
            if (aok) { ra0 = *(const float4*)(ap); ra1 = *(const float4*)(ap + 4); }
            const float* bp = bptr + (size_t)(k0 + 16) * 1024;
            rb0 = *(const float4*)(bp);
            rb1 = *(const float4*)(bp + 4);
        }

        // MMA: one k16 step per tile
        {
            wmma::fragment<wmma::matrix_a, 16, 16, 16, __half, wmma::row_major> af[4];
            wmma::fragment<wmma::matrix_b, 16, 16, 16, __half, wmma::row_major> bf[2];
#pragma unroll
            for (int i = 0; i < 4; i++)
                wmma::load_matrix_sync(af[i], &sA[(wm * 64 + i * 16) * ALDH], ALDH);
#pragma unroll
            for (int j = 0; j < 2; j++)
                wmma::load_matrix_sync(bf[j], &sB[wn * 32 + j * 16], BLDH);
#pragma unroll
            for (int i = 0; i < 4; i++)
#pragma unroll
                for (int j = 0; j < 2; j++)
                    wmma::mma_sync(acc[i][j], af[i], bf[j], acc[i][j]);
        }
    }

    // epilogue: stage 64x16 per warp (fp32), add bias, store (rows padded -> no guard)
    float* stage = sh + wid * 1024;
#pragma unroll
    for (int j = 0; j < 2; j++) {
        if (j == 0) __syncthreads();       // mainloop smem dead for all warps
#pragma unroll
        for (int i = 0; i < 4; i++)
            wmma::store_matrix_sync(&stage[i * 256], acc[i][j], 16, wmma::mem_row_major);
        __syncwarp();
        int row0 = m0 + wm * 64;
        int col0 = n0 + wn * 32 + j * 16;
#pragma unroll
        for (int it = 0; it < 8; it++) {
            int f = it * 128 + lane * 4;
            int r = f >> 4, c = f & 15;
            float4 v = *(float4*)&stage[f];
            float4 bv = *(const float4*)&bias[col0 + c];
            v.x += bv.x; v.y += bv.y; v.z += bv.z; v.w += bv.w;
            size_t o = (size_t)(row0 + r) * 1024 + col0 + c;
            if (blockIdx.z == 0) {
                __half2 p0 = __floats2half2_rn(v.x, v.y);
                __half2 p1 = __floats2half2_rn(v.z, v.w);
                uint2 raw = make_uint2(*(unsigned*)&p0, *(unsigned*)&p1);
                *(uint2*)&Chl[o] = raw;
            } else {
                *(float4*)&Cr[o] = v;
            }
        }
        __syncwarp();
    }
}

// ---------------- fused edge attention + softmax + aggregation ----------------
__device__ __forceinline__ float4 ldx_f16(const __half* p) {
    uint2 raw = *(const uint2*)p;
    __half2 h01 = *(__half2*)&raw.x;
    __half2 h23 = *(__half2*)&raw.y;
    float2 f01 = __half22float2(h01);
    float2 f23 = __half22float2(h23);
    return make_float4(f01.x, f01.y, f23.x, f23.y);
}

__device__ __forceinline__ float dot_leaky(float4 v, float4 r, float4 t) {
    float z0 = v.x + r.x; z0 = z0 > 0.f ? z0 : 0.2f * z0;
    float z1 = v.y + r.y; z1 = z1 > 0.f ? z1 : 0.2f * z1;
    float z2 = v.z + r.z; z2 = z2 > 0.f ? z2 : 0.2f * z2;
    float z3 = v.w + r.w; z3 = z3 > 0.f ? z3 : 0.2f * z3;
    return t.x * z0 + t.y * z1 + t.z * z2 + t.w * z3;
}

// block per destination node; warp h owns head h.
// csr indices staged in smem once per 128-edge chunk (kills 8x redundant LDG
// and the per-warp dependent index->row load chain); 4-way unrolled body.
__global__ __launch_bounds__(256)
void k_edge(const __half* __restrict__ xlh, const float* __restrict__ xr,
            const float* __restrict__ att,
            const int* __restrict__ off, const int* __restrict__ csr,
            const float* __restrict__ bias, float* __restrict__ out) {
    int n = blockIdx.x;
    int tid = threadIdx.x, h = tid >> 5, lane = tid & 31;
    __shared__ float sacc[HC];
    __shared__ int sidx[128];
    int base = h * CC + lane * 4;
    float4 r4 = *(const float4*)&xr[(size_t)n * HC + base];
    float4 t4 = *(const float4*)&att[base];
    int beg = off[n], end = off[n + 1];
    float4 acc = make_float4(0.f, 0.f, 0.f, 0.f);
    float den = 1e-16f;

    for (int c0 = beg; c0 < end; c0 += 128) {
        int m = end - c0;
        if (m > 128) m = 128;
        __syncthreads();                       // sidx safe to overwrite
        if (tid < m) sidx[tid] = csr[c0 + tid];
        __syncthreads();
        int e = 0;
        for (; e + 4 <= m; e += 4) {
            int s0 = sidx[e], s1 = sidx[e + 1], s2 = sidx[e + 2], s3 = sidx[e + 3];
            float4 u0 = ldx_f16(&xlh[(size_t)s0 * HC + base]);
            float4 u1 = ldx_f16(&xlh[(size_t)s1 * HC + base]);
            float4 u2 = ldx_f16(&xlh[(size_t)s2 * HC + base]);
            float4 u3 = ldx_f16(&xlh[(size_t)s3 * HC + base]);
            float a0 = dot_leaky(u0, r4, t4);
            float a1 = dot_leaky(u1, r4, t4);
            float a2 = dot_leaky(u2, r4, t4);
            float a3 = dot_leaky(u3, r4, t4);
#pragma unroll
            for (int o = 16; o; o >>= 1) {
                a0 += __shfl_xor_sync(0xffffffffu, a0, o);
                a1 += __shfl_xor_sync(0xffffffffu, a1, o);
                a2 += __shfl_xor_sync(0xffffffffu, a2, o);
                a3 += __shfl_xor_sync(0xffffffffu, a3, o);
            }
            float w0 = __expf(a0), w1 = __expf(a1), w2 = __expf(a2), w3 = __expf(a3);
            acc.x += w0 * u0.x + w1 * u1.x + w2 * u2.x + w3 * u3.x;
            acc.y += w0 * u0.y + w1 * u1.y + w2 * u2.y + w3 * u3.y;
            acc.z += w0 * u0.z + w1 * u1.z + w2 * u2.z + w3 * u3.z;
            acc.w += w0 * u0.w + w1 * u1.w + w2 * u2.w + w3 * u3.w;
            den += (w0 + w1) + (w2 + w3);
        }
        for (; e < m; e++) {
            int s0 = sidx[e];
            float4 u4 = ldx_f16(&xlh[(size_t)s0 * HC + base]);
            float a = dot_leaky(u4, r4, t4);
#pragma unroll
            for (int o = 16; o; o >>= 1) a += __shfl_xor_sync(0xffffffffu, a, o);
            float wa = __expf(a);
            acc.x += wa * u4.x;
            acc.y += wa * u4.y;
            acc.z += wa * u4.z;
            acc.w += wa * u4.w;
            den += wa;
        }
    }

    float rd = 1.0f / den;
    acc.x *= rd; acc.y *= rd; acc.z *= rd; acc.w *= rd;
    *(float4*)&sacc[base] = acc;
    __syncthreads();
    if (tid < CC) {
        float s = 0.f;
#pragma unroll
        for (int hh = 0; hh < HH; hh++) s += sacc[hh * CC + tid];
        s = s * 0.125f + bias[tid];
        if (s < 0.f) s = 0.f;
        out[(size_t)n * CC + tid] = s;
    }
}

// ---------------- final linear on drone rows ----------------
__global__ void k_out(const float* __restrict__ h2, const float* __restrict__ W,
                      const float* __restrict__ b, const int* __restrict__ rows,
                      float* __restrict__ out) {
    int idx = blockIdx.x * blockDim.x + threadIdx.x;
    if (idx >= NAG * COUT) return;
    int r = idx >> 3, j = idx & 7;
    int node = rows[r];
    float s = b[j];
    const float* hr = &h2[(size_t)node * CC];
#pragma unroll 4
    for (int k = 0; k < CC; k++) s += hr[k] * W[k * COUT + j];
    out[idx] = s;
}

// ---------------- launch ----------------
extern "C" void kernel_launch(void* const* d_in, const int* in_sizes, int n_in,
                              void* d_out, int out_size) {
    const float* x = (const float*)d_in[0];
    const int* ei = (const int*)d_in[1];
    const float* Wl1 = (const float*)d_in[2];
    const float* bl1 = (const float*)d_in[3];
    const float* Wr1 = (const float*)d_in[4];
    const float* br1 = (const float*)d_in[5];
    const float* att1 = (const float*)d_in[6];
    const float* b1 = (const float*)d_in[7];
    const float* Wl2 = (const float*)d_in[8];
    const float* bl2 = (const float*)d_in[9];
    const float* Wr2 = (const float*)d_in[10];
    const float* br2 = (const float*)d_in[11];
    const float* att2 = (const float*)d_in[12];
    const float* b2 = (const float*)d_in[13];
    const float* Wlin = (const float*)d_in[14];
    const float* blin = (const float*)d_in[15];
    float* out = (float*)d_out;

    __half* xlh;
    float *xr, *h1, *h2;
    int *deg, *wp, *off, *csr, *rows;
    cudaGetSymbolAddress((void**)&xlh, g_xlh);
    cudaGetSymbolAddress((void**)&xr, g_xr);
    cudaGetSymbolAddress((void**)&h1, g_h1);
    cudaGetSymbolAddress((void**)&h2, g_h2);
    cudaGetSymbolAddress((void**)&deg, g_deg);
    cudaGetSymbolAddress((void**)&wp, g_wp);
    cudaGetSymbolAddress((void**)&off, g_off);
    cudaGetSymbolAddress((void**)&csr, g_csr);
    cudaGetSymbolAddress((void**)&rows, g_rows);

    const int TPB = 256;
    dim3 gGemm(1024 / 128, NP / 128, 2);   // 8 x 79 x 2 (z: Wl-fp16 / Wr-fp32)

    // CSR build (shared by both layers)
    k_zero1<<<(NN + TPB - 1) / TPB, TPB>>>(deg, NN);
    k_count<<<(ET + TPB - 1) / TPB, TPB>>>(ei, deg);
    k_scan<<<1, 1024>>>(deg, off, wp);
    k_fill<<<(ET + TPB - 1) / TPB, TPB>>>(ei, wp, csr);

    // Layer 1 (K=16)
    k_gemm2<16><<<gGemm, TPB>>>(x, Wl1, bl1, xlh, Wr1, br1, xr, NN);
    k_edge<<<NN, TPB>>>(xlh, xr, att1, off, csr, b1, h1);

    // Layer 2 (K=128)
    k_gemm2<128><<<gGemm, TPB>>>(h1, Wl2, bl2, xlh, Wr2, br2, xr, NP);
    k_edge<<<NN, TPB>>>(xlh, xr, att2, off, csr, b2, h2);

    // Drone rows + output projection (off the critical front)
    k_rows<<<1, 1024>>>(x, rows);
    k_out<<<(NAG * COUT + TPB - 1) / TPB, TPB>>>(h2, Wlin, blin, rows, out);
}

// round 16
// speedup vs baseline: 1.0025x; 1.0025x over previous
#include <cuda_runtime.h>
#include <cuda_fp16.h>
#include <mma.h>
using namespace nvcuda;

#define NN 10000
#define NP 10112    /* padded to 79*128 for unguarded wmma stores */
#define NAG 5000
#define EE 160000
#define ET 170000   /* EE + NN self-loops */
#define HH 8
#define CC 128
#define HC 1024     /* HH*CC */
#define COUT 8

// ---------------- scratch (device globals; no allocation allowed) ----------------
__device__ __align__(16) __half g_xlh[NP * HC];   // xl in fp16 (edge-pass stream)
__device__ __align__(16) float g_xr[NP * HC];     // xr fp32 (read once per node)
__device__ __align__(16) float g_h1[NP * CC];     // pad rows stay zero (.bss)
__device__ __align__(16) float g_h2[NP * CC];
__device__ int g_deg[NN];
__device__ int g_wp[NN];
__device__ int g_off[NN + 1];
__device__ int g_csr[ET];
__device__ int g_rows[NAG];

// ---------------- CSR build ----------------
__global__ void k_zero1(int* a, int n) {
    int i = blockIdx.x * blockDim.x + threadIdx.x;
    if (i < n) a[i] = 0;
}

__global__ void k_count(const int* __restrict__ ei, int* __restrict__ deg) {
    int e = blockIdx.x * blockDim.x + threadIdx.x;
    if (e >= ET) return;
    int dst = (e < EE) ? ei[EE + e] : (e - EE);
    atomicAdd(&deg[dst], 1);
}

// 1024 threads, 10 items/thread, warp-shuffle two-level exclusive scan.
// Also seeds wp[i] = off[i] so k_fill needs a single atomicAdd.
__global__ void k_scan(const int* __restrict__ deg, int* __restrict__ off,
                       int* __restrict__ wp) {
    __shared__ int wsum[32];
    int tid = threadIdx.x, lane = tid & 31, wid = tid >> 5;
    int base = tid * 10;
    int loc[10];
    int s = 0;
#pragma unroll
    for (int i = 0; i < 10; i++) {
        int idx = base + i;
        int v = (idx < NN) ? deg[idx] : 0;
        loc[i] = s;
        s += v;
    }
    int inc = s;
#pragma unroll
    for (int o = 1; o < 32; o <<= 1) {
        int t = __shfl_up_sync(0xffffffffu, inc, o);
        if (lane >= o) inc += t;
    }
    if (lane == 31) wsum[wid] = inc;
    __syncthreads();
    if (wid == 0) {
        int w = wsum[lane];
        int wi = w;
#pragma unroll
        for (int o = 1; o < 32; o <<= 1) {
            int t = __shfl_up_sync(0xffffffffu, wi, o);
            if (lane >= o) wi += t;
        }
        wsum[lane] = wi - w;
        if (lane == 31) off[NN] = wi;
    }
    __syncthreads();
    int pre = wsum[wid] + inc - s;
#pragma unroll
    for (int i = 0; i < 10; i++) {
        int idx = base + i;
        if (idx < NN) {
            int v = pre + loc[i];
            off[idx] = v;
            wp[idx] = v;
        }
    }
}

__global__ void k_fill(const int* __restrict__ ei, int* __restrict__ wp,
                       int* __restrict__ csr) {
    int e = blockIdx.x * blockDim.x + threadIdx.x;
    if (e >= ET) return;
    int src, dst;
    if (e < EE) { src = ei[e]; dst = ei[EE + e]; }
    else        { src = e - EE; dst = src; }
    int p = atomicAdd(&wp[dst], 1);
    csr[p] = src;
}

// Drone row gather list (stable compaction).
__global__ void k_rows(const float* __restrict__ x, int* __restrict__ rows) {
    __shared__ int wsum[32];
    int tid = threadIdx.x, lane = tid & 31, wid = tid >> 5;
    int base = tid * 10;
    int loc[10], msk[10];
    int s = 0;
#pragma unroll
    for (int i = 0; i < 10; i++) {
        int idx = base + i;
        int v = (idx < NN && x[idx * 16 + 15] < 0.f) ? 1 : 0;
        msk[i] = v;
        loc[i] = s;
        s += v;
    }
    int inc = s;
#pragma unroll
    for (int o = 1; o < 32; o <<= 1) {
        int t = __shfl_up_sync(0xffffffffu, inc, o);
        if (lane >= o) inc += t;
    }
    if (lane == 31) wsum[wid] = inc;
    __syncthreads();
    if (wid == 0) {
        int w = wsum[lane];
        int wi = w;
#pragma unroll
        for (int o = 1; o < 32; o <<= 1) {
            int t = __shfl_up_sync(0xffffffffu, wi, o);
            if (lane >= o) wi += t;
        }
        wsum[lane] = wi - w;
    }
    __syncthreads();
    int pre = wsum[wid] + inc - s;
#pragma unroll
    for (int i = 0; i < 10; i++) {
        int idx = base + i;
        if (msk[i]) {
            int pos = pre + loc[i];
            if (pos < NAG) rows[pos] = idx;
        }
    }
}

// ---------------- merged fp16 GEMM: z=0: Ch_l = A@Bl+bl (fp16); z=1: Cr = A@Br+br (fp32)
// BM=128, BN=128, BK=16, 256 threads, 8 warps x (64x32), wmma m16n16k16 half, fp32 acc.
// K is a template constant -> fully unrolled mainloop; double-buffered smem.
#define ALDH 24     /* A tile leading dim in halves (16 + 8 pad) */
#define BLDH 136    /* B tile leading dim in halves (128 + 8 pad) */
#define SH_A0 0
#define SH_A1 (128 * ALDH)                 /* 3072 */
#define SH_B0 (2 * 128 * ALDH)             /* 6144 */
#define SH_B1 (SH_B0 + 16 * BLDH)          /* 8320 */
template <int K>
__global__ __launch_bounds__(256)
void k_gemm2(const float* __restrict__ A,
             const float* __restrict__ Bl, const float* __restrict__ bl,
             __half* __restrict__ Chl,
             const float* __restrict__ Br, const float* __restrict__ br,
             float* __restrict__ Cr,
             int M) {
    __shared__ float sh[8192];             // 32KB; halves alias during mainloop
    __half* shh = (__half*)sh;

    const float* B = (blockIdx.z == 0) ? Bl : Br;
    const float* bias = (blockIdx.z == 0) ? bl : br;

    int tid = threadIdx.x;
    int wid = tid >> 5, lane = tid & 31;
    int wm = wid >> 2, wn = wid & 3;
    int m0 = blockIdx.y * 128, n0 = blockIdx.x * 128;

    int arow = tid >> 1;                   // 0..127
    int akb = (tid & 1) * 8;               // 0 or 8
    int brow = tid >> 4;                   // 0..15
    int bcol = (tid & 15) * 8;             // 0..120

    bool aok = (m0 + arow < M);
    const float* aptr = &A[(size_t)(m0 + arow) * K + akb];
    const float* bptr = &B[(size_t)brow * 1024 + n0 + bcol];

    wmma::fragment<wmma::accumulator, 16, 16, 16, float> acc[4][2];
#pragma unroll
    for (int i = 0; i < 4; i++)
#pragma unroll
        for (int j = 0; j < 2; j++) wmma::fill_fragment(acc[i][j], 0.f);

    // prologue: load tile 0 into registers
    float4 ra0 = make_float4(0.f, 0.f, 0.f, 0.f), ra1 = ra0;
    if (aok) { ra0 = *(const float4*)(aptr); ra1 = *(const float4*)(aptr + 4); }
    float4 rb0 = *(const float4*)(bptr);
    float4 rb1 = *(const float4*)(bptr + 4);

#pragma unroll
    for (int k0 = 0; k0 < K; k0 += 16) {
        const int buf = (k0 >> 4) & 1;
        __half* sA = shh + (buf ? SH_A1 : SH_A0);
        __half* sB = shh + (buf ? SH_B1 : SH_B0);
        {
            __half2* ap2 = (__half2*)&sA[arow * ALDH + akb];
            ap2[0] = __floats2half2_rn(ra0.x, ra0.y);
            ap2[1] = __floats2half2_rn(ra0.z, ra0.w);
            ap2[2] = __floats2half2_rn(ra1.x, ra1.y);
            ap2[3] = __floats2half2_rn(ra1.z, ra1.w);
            __half2* bp2 = (__half2*)&sB[brow * BLDH + bcol];
            bp2[0] = __floats2half2_rn(rb0.x, rb0.y);
            bp2[1] = __floats2half2_rn(rb0.z, rb0.w);
            bp2[2] = __floats2half2_rn(rb1.x, rb1.y);
            bp2[3] = __floats2half2_rn(rb1.z, rb1.w);
        }
        __syncthreads();

        // prefetch next tile into registers (overlaps MMA below)
        if (k0 + 16 < K) {
            const float* ap = aptr + k0 + 16;
            ra0 = make_float4(0.f, 0.f, 0.f, 0.f); ra1 = ra0;
            if (aok) { ra0 = *(const float4*)(ap); ra1 = *(const float4*)(ap + 4); }
            const float* bp = bptr + (size_t)(k0 + 16) * 1024;
            rb0 = *(const float4*)(bp);
            rb1 = *(const float4*)(bp + 4);
        }

        // MMA: one k16 step per tile
        {
            wmma::fragment<wmma::matrix_a, 16, 16, 16, __half, wmma::row_major> af[4];
            wmma::fragment<wmma::matrix_b, 16, 16, 16, __half, wmma::row_major> bf[2];
#pragma unroll
            for (int i = 0; i < 4; i++)
                wmma::load_matrix_sync(af[i], &sA[(wm * 64 + i * 16) * ALDH], ALDH);
#pragma unroll
            for (int j = 0; j < 2; j++)
                wmma::load_matrix_sync(bf[j], &sB[wn * 32 + j * 16], BLDH);
#pragma unroll
            for (int i = 0; i < 4; i++)
#pragma unroll
                for (int j = 0; j < 2; j++)
                    wmma::mma_sync(acc[i][j], af[i], bf[j], acc[i][j]);
        }
    }

    // epilogue: stage 64x16 per warp (fp32), add bias, store (rows padded -> no guard)
    float* stage = sh + wid * 1024;
#pragma unroll
    for (int j = 0; j < 2; j++) {
        if (j == 0) __syncthreads();       // mainloop smem dead for all warps
#pragma unroll
        for (int i = 0; i < 4; i++)
            wmma::store_matrix_sync(&stage[i * 256], acc[i][j], 16, wmma::mem_row_major);
        __syncwarp();
        int row0 = m0 + wm * 64;
        int col0 = n0 + wn * 32 + j * 16;
#pragma unroll
        for (int it = 0; it < 8; it++) {
            int f = it * 128 + lane * 4;
            int r = f >> 4, c = f & 15;
            float4 v = *(float4*)&stage[f];
            float4 bv = *(const float4*)&bias[col0 + c];
            v.x += bv.x; v.y += bv.y; v.z += bv.z; v.w += bv.w;
            size_t o = (size_t)(row0 + r) * 1024 + col0 + c;
            if (blockIdx.z == 0) {
                __half2 p0 = __floats2half2_rn(v.x, v.y);
                __half2 p1 = __floats2half2_rn(v.z, v.w);
                uint2 raw = make_uint2(*(unsigned*)&p0, *(unsigned*)&p1);
                *(uint2*)&Chl[o] = raw;
            } else {
                *(float4*)&Cr[o] = v;
            }
        }
        __syncwarp();
    }
}

// ---------------- fused edge attention + softmax + aggregation ----------------
__device__ __forceinline__ float4 ldx_f16(const __half* p) {
    uint2 raw = *(const uint2*)p;
    __half2 h01 = *(__half2*)&raw.x;
    __half2 h23 = *(__half2*)&raw.y;
    float2 f01 = __half22float2(h01);
    float2 f23 = __half22float2(h23);
    return make_float4(f01.x, f01.y, f23.x, f23.y);
}

__device__ __forceinline__ float dot_leaky(float4 v, float4 r, float4 t) {
    float z0 = v.x + r.x; z0 = z0 > 0.f ? z0 : 0.2f * z0;
    float z1 = v.y + r.y; z1 = z1 > 0.f ? z1 : 0.2f * z1;
    float z2 = v.z + r.z; z2 = z2 > 0.f ? z2 : 0.2f * z2;
    float z3 = v.w + r.w; z3 = z3 > 0.f ? z3 : 0.2f * z3;
    return t.x * z0 + t.y * z1 + t.z * z2 + t.w * z3;
}

// block per destination node; warp h owns head h.
// csr indices staged in smem once per 128-edge chunk (kills 8x redundant LDG
// and the per-warp dependent index->row load chain); 4-way unrolled body.
__global__ __launch_bounds__(256)
void k_edge(const __half* __restrict__ xlh, const float* __restrict__ xr,
            const float* __restrict__ att,
            const int* __restrict__ off, const int* __restrict__ csr,
            const float* __restrict__ bias, float* __restrict__ out) {
    int n = blockIdx.x;
    int tid = threadIdx.x, h = tid >> 5, lane = tid & 31;
    __shared__ float sacc[HC];
    __shared__ int sidx[128];
    int base = h * CC + lane * 4;
    float4 r4 = *(const float4*)&xr[(size_t)n * HC + base];
    float4 t4 = *(const float4*)&att[base];
    int beg = off[n], end = off[n + 1];
    float4 acc = make_float4(0.f, 0.f, 0.f, 0.f);
    float den = 1e-16f;

    for (int c0 = beg; c0 < end; c0 += 128) {
        int m = end - c0;
        if (m > 128) m = 128;
        __syncthreads();                       // sidx safe to overwrite
        if (tid < m) sidx[tid] = csr[c0 + tid];
        __syncthreads();
        int e = 0;
        for (; e + 4 <= m; e += 4) {
            int s0 = sidx[e], s1 = sidx[e + 1], s2 = sidx[e + 2], s3 = sidx[e + 3];
            float4 u0 = ldx_f16(&xlh[(size_t)s0 * HC + base]);
            float4 u1 = ldx_f16(&xlh[(size_t)s1 * HC + base]);
            float4 u2 = ldx_f16(&xlh[(size_t)s2 * HC + base]);
            float4 u3 = ldx_f16(&xlh[(size_t)s3 * HC + base]);
            float a0 = dot_leaky(u0, r4, t4);
            float a1 = dot_leaky(u1, r4, t4);
            float a2 = dot_leaky(u2, r4, t4);
            float a3 = dot_leaky(u3, r4, t4);
#pragma unroll
            for (int o = 16; o; o >>= 1) {
                a0 += __shfl_xor_sync(0xffffffffu, a0, o);
                a1 += __shfl_xor_sync(0xffffffffu, a1, o);
                a2 += __shfl_xor_sync(0xffffffffu, a2, o);
                a3 += __shfl_xor_sync(0xffffffffu, a3, o);
            }
            float w0 = __expf(a0), w1 = __expf(a1), w2 = __expf(a2), w3 = __expf(a3);
            acc.x += w0 * u0.x + w1 * u1.x + w2 * u2.x + w3 * u3.x;
            acc.y += w0 * u0.y + w1 * u1.y + w2 * u2.y + w3 * u3.y;
            acc.z += w0 * u0.z + w1 * u1.z + w2 * u2.z + w3 * u3.z;
            acc.w += w0 * u0.w + w1 * u1.w + w2 * u2.w + w3 * u3.w;
            den += (w0 + w1) + (w2 + w3);
        }
        for (; e < m; e++) {
            int s0 = sidx[e];
            float4 u4 = ldx_f16(&xlh[(size_t)s0 * HC + base]);
            float a = dot_leaky(u4, r4, t4);
#pragma unroll
            for (int o = 16; o; o >>= 1) a += __shfl_xor_sync(0xffffffffu, a, o);
            float wa = __expf(a);
            acc.x += wa * u4.x;
            acc.y += wa * u4.y;
            acc.z += wa * u4.z;
            acc.w += wa * u4.w;
            den += wa;
        }
    }

    float rd = 1.0f / den;
    acc.x *= rd; acc.y *= rd; acc.z *= rd; acc.w *= rd;
    *(float4*)&sacc[base] = acc;
    __syncthreads();
    if (tid < CC) {
        float s = 0.f;
#pragma unroll
        for (int hh = 0; hh < HH; hh++) s += sacc[hh * CC + tid];
        s = s * 0.125f + bias[tid];
        if (s < 0.f) s = 0.f;
        out[(size_t)n * CC + tid] = s;
    }
}

// ---------------- final linear on drone rows ----------------
__global__ void k_out(const float* __restrict__ h2, const float* __restrict__ W,
                      const float* __restrict__ b, const int* __restrict__ rows,
                      float* __restrict__ out) {
    int idx = blockIdx.x * blockDim.x + threadIdx.x;
    if (idx >= NAG * COUT) return;
    int r = idx >> 3, j = idx & 7;
    int node = rows[r];
    float s = b[j];
    const float* hr = &h2[(size_t)node * CC];
#pragma unroll 4
    for (int k = 0; k < CC; k++) s += hr[k] * W[k * COUT + j];
    out[idx] = s;
}

// ---------------- launch ----------------
extern "C" void kernel_launch(void* const* d_in, const int* in_sizes, int n_in,
                              void* d_out, int out_size) {
    const float* x = (const float*)d_in[0];
    const int* ei = (const int*)d_in[1];
    const float* Wl1 = (const float*)d_in[2];
    const float* bl1 = (const float*)d_in[3];
    const float* Wr1 = (const float*)d_in[4];
    const float* br1 = (const float*)d_in[5];
    const float* att1 = (const float*)d_in[6];
    const float* b1 = (const float*)d_in[7];
    const float* Wl2 = (const float*)d_in[8];
    const float* bl2 = (const float*)d_in[9];
    const float* Wr2 = (const float*)d_in[10];
    const float* br2 = (const float*)d_in[11];
    const float* att2 = (const float*)d_in[12];
    const float* b2 = (const float*)d_in[13];
    const float* Wlin = (const float*)d_in[14];
    const float* blin = (const float*)d_in[15];
    float* out = (float*)d_out;

    __half* xlh;
    float *xr, *h1, *h2;
    int *deg, *wp, *off, *csr, *rows;
    cudaGetSymbolAddress((void**)&xlh, g_xlh);
    cudaGetSymbolAddress((void**)&xr, g_xr);
    cudaGetSymbolAddress((void**)&h1, g_h1);
    cudaGetSymbolAddress((void**)&h2, g_h2);
    cudaGetSymbolAddress((void**)&deg, g_deg);
    cudaGetSymbolAddress((void**)&wp, g_wp);
    cudaGetSymbolAddress((void**)&off, g_off);
    cudaGetSymbolAddress((void**)&csr, g_csr);
    cudaGetSymbolAddress((void**)&rows, g_rows);

    const int TPB = 256;
    dim3 gGemm(1024 / 128, NP / 128, 2);   // 8 x 79 x 2 (z: Wl-fp16 / Wr-fp32)

    // CSR build (shared by both layers)
    k_zero1<<<(NN + TPB - 1) / TPB, TPB>>>(deg, NN);
    k_count<<<(ET + TPB - 1) / TPB, TPB>>>(ei, deg);
    k_scan<<<1, 1024>>>(deg, off, wp);
    k_fill<<<(ET + TPB - 1) / TPB, TPB>>>(ei, wp, csr);

    // Layer 1 (K=16)
    k_gemm2<16><<<gGemm, TPB>>>(x, Wl1, bl1, xlh, Wr1, br1, xr, NN);
    k_edge<<<NN, TPB>>>(xlh, xr, att1, off, csr, b1, h1);

    // Layer 2 (K=128)
    k_gemm2<128><<<gGemm, TPB>>>(h1, Wl2, bl2, xlh, Wr2, br2, xr, NP);
    k_edge<<<NN, TPB>>>(xlh, xr, att2, off, csr, b2, h2);

    // Drone rows + output projection (off the critical front)
    k_rows<<<1, 1024>>>(x, rows);
    k_out<<<(NAG * COUT + TPB - 1) / TPB, TPB>>>(h2, Wlin, blin, rows, out);
}